// round 9
// baseline (speedup 1.0000x reference)
#include <cuda_runtime.h>
#include <float.h>

#define D      8192
#define D4     2048          // D / 4 (float4 per row)
#define GAMMA  0.95f
#define NSLAB  64            // row slabs in kernel 1
#define RSLAB  128           // rows per slab (NSLAB * RSLAB = D)
#define CTILE  8             // column tiles (CTILE * 1024 = D)

// ---------------- device scratch (no allocations allowed) ----------------
__device__ float g_part_dot[NSLAB][D];   // fully rewritten every call
__device__ float g_part_sq [NSLAB][D];
__device__ float g_ev   [D];             // exp(sim_j), written by k1b
__device__ float g_evsum[64];            // per-block partial sums of ev
__device__ float g_knorm;                // ||k||
__device__ float g_wr  [D];              // w_r with column min_idx zeroed
__device__ float g_addk[D];              // w_u_new * k (per column add for mk)
__device__ float g_addu[D];              // w_w_new * u (per column add for mu)
__device__ int   g_min_idx;

// output layout (element offsets into d_out, float32)
#define OFF_UF  ((size_t)0)
#define OFF_MK  ((size_t)D)
#define OFF_MU  ((size_t)D + (size_t)D * D)
#define OFF_WW  ((size_t)D + 2ull * (size_t)D * D)
#define OFF_WU  (OFF_WW + (size_t)D)
#define OFF_WLU (OFF_WU + (size_t)D)

// ---------------- warp helpers ----------------
__device__ __forceinline__ float warp_sum(float v) {
#pragma unroll
    for (int o = 16; o > 0; o >>= 1) v += __shfl_xor_sync(0xffffffffu, v, o);
    return v;
}
__device__ __forceinline__ float warp_min(float v) {
#pragma unroll
    for (int o = 16; o > 0; o >>= 1) v = fminf(v, __shfl_xor_sync(0xffffffffu, v, o));
    return v;
}

// ---------------- kernel 0: ||k|| and argmin(w_u) (1 block) ----------------
__global__ __launch_bounds__(1024) void k0_prep(const float* __restrict__ kvec,
                                                const float* __restrict__ w_u)
{
    const int tid  = threadIdx.x;
    const int lane = tid & 31;
    const int wid  = tid >> 5;

    __shared__ float sredf[32];
    __shared__ int   sredi[32];

    float ks = 0.f;
    float bestv = FLT_MAX;
    int   besti = 0x7fffffff;
#pragma unroll
    for (int p = 0; p < 8; ++p) {
        int j = tid + p * 1024;
        float kj = kvec[j];
        ks += kj * kj;
        float wuj = w_u[j];
        if (wuj < bestv || (wuj == bestv && j < besti)) { bestv = wuj; besti = j; }
    }
    // ||k||^2 reduction
    {
        float v = warp_sum(ks);
        if (lane == 0) sredf[wid] = v;
        __syncthreads();
        if (tid < 32) {
            float t = warp_sum(sredf[tid]);
            if (tid == 0) g_knorm = sqrtf(t);
        }
        __syncthreads();
    }
    // first-index argmin reduction
    {
#pragma unroll
        for (int o = 16; o > 0; o >>= 1) {
            float ov = __shfl_xor_sync(0xffffffffu, bestv, o);
            int   oi = __shfl_xor_sync(0xffffffffu, besti, o);
            if (ov < bestv || (ov == bestv && oi < besti)) { bestv = ov; besti = oi; }
        }
        if (lane == 0) { sredf[wid] = bestv; sredi[wid] = besti; }
        __syncthreads();
        if (tid < 32) {
            float bv = sredf[tid];
            int   bi = sredi[tid];
#pragma unroll
            for (int o = 16; o > 0; o >>= 1) {
                float ov = __shfl_xor_sync(0xffffffffu, bv, o);
                int   oi = __shfl_xor_sync(0xffffffffu, bi, o);
                if (ov < bv || (ov == bv && oi < bi)) { bv = ov; bi = oi; }
            }
            if (tid == 0) g_min_idx = bi;
        }
    }
}

// ---------------- kernel 1: partial column reductions over mk ----------------
// EXACT Round-3 configuration (best measured): grid (8,64), block 256,
// explicit 8-deep load batching, __ldcs on the mk stream. FROZEN.
__global__ __launch_bounds__(256) void k1_colred(const float* __restrict__ mk,
                                                 const float* __restrict__ kvec)
{
    __shared__ float sk[RSLAB];
    const int ct  = blockIdx.x;
    const int rs  = blockIdx.y;
    const int tid = threadIdx.x;
    const int row0 = rs * RSLAB;

    if (tid < RSLAB) sk[tid] = kvec[row0 + tid];
    __syncthreads();

    const int col4 = ct * 256 + tid;   // float4 column index within row
    const float4* __restrict__ mk4 = (const float4*)mk + (size_t)row0 * D4 + col4;

    float4 ad = make_float4(0.f, 0.f, 0.f, 0.f);
    float4 as = make_float4(0.f, 0.f, 0.f, 0.f);

    for (int r = 0; r < RSLAB; r += 8) {
        float4 v[8];
#pragma unroll
        for (int i = 0; i < 8; ++i)
            v[i] = __ldcs(mk4 + (size_t)(r + i) * D4);
#pragma unroll
        for (int i = 0; i < 8; ++i) {
            float kr = sk[r + i];
            ad.x += kr * v[i].x; ad.y += kr * v[i].y;
            ad.z += kr * v[i].z; ad.w += kr * v[i].w;
            as.x += v[i].x * v[i].x; as.y += v[i].y * v[i].y;
            as.z += v[i].z * v[i].z; as.w += v[i].w * v[i].w;
        }
    }

    ((float4*)g_part_dot[rs])[col4] = ad;
    ((float4*)g_part_sq [rs])[col4] = as;
}

// ---------------- kernel 1b: slab reduction + cosine + exp (64 x 128) -------
// sim is a cosine in [-1,1] so exp(sim) cannot overflow: the softmax
// max-subtraction is mathematically redundant (shift-invariant) and dropped.
// The 8192 exps now run on 64 SMs instead of one.
__global__ __launch_bounds__(128) void k1b_simexp()
{
    __shared__ float sred[4];
    const int tid = threadIdx.x;
    const int j   = blockIdx.x * 128 + tid;

    float sd = 0.f, ss = 0.f;
#pragma unroll
    for (int s = 0; s < NSLAB; ++s) {
        sd += g_part_dot[s][j];
        ss += g_part_sq [s][j];
    }
    const float ev = __expf(sd / (g_knorm * sqrtf(ss)));
    g_ev[j] = ev;

    // deterministic block-level sum of ev (4 warps)
    float v = warp_sum(ev);
    if ((tid & 31) == 0) sred[tid >> 5] = v;
    __syncthreads();
    if (tid == 0)
        g_evsum[blockIdx.x] = (sred[0] + sred[1]) + (sred[2] + sred[3]);
}

// ---------------- kernel 2: vector epilogue, no exps (1 block, 1024 thr) ----
__global__ __launch_bounds__(1024) void k2_vec(const float* __restrict__ kvec,
                                               const float* __restrict__ uvec,
                                               const float* __restrict__ w_w,
                                               const float* __restrict__ w_u,
                                               const float* __restrict__ w_lu,
                                               const float* __restrict__ beta_p,
                                               float* __restrict__ out)
{
    const int tid  = threadIdx.x;
    const int lane = tid & 31;
    const int wid  = tid >> 5;

    __shared__ float sredf[32];
    __shared__ float s_sum, s_min;

    // ---- softmax denominator from the 64 per-block partials ----
    if (tid < 32) {
        float t = g_evsum[tid] + g_evsum[tid + 32];
        t = warp_sum(t);
        if (tid == 0) s_sum = t;
    }
    __syncthreads();
    const float inv_sum = 1.f / s_sum;
    const float beta    = 1.f / (1.f + __expf(-beta_p[0]));
    const int   minidx  = g_min_idx;

    // ---- w_r, w_u_new, w_w_new, add-vectors + min(w_u_new) ----
    float wun[8];
    float lmin = FLT_MAX;
#pragma unroll
    for (int p = 0; p < 8; ++p) {
        int j = tid + p * 1024;
        float wr     = g_ev[j] * inv_sum;
        float wu_new = GAMMA * w_u[j] + wr + w_w[j];
        float ww_new = beta * wr + (1.f - beta) * w_lu[j];
        wun[p] = wu_new;
        lmin = fminf(lmin, wu_new);
        out[OFF_WU + j] = wu_new;
        out[OFF_WW + j] = ww_new;
        g_addk[j] = wu_new * kvec[j];
        g_addu[j] = ww_new * uvec[j];
        g_wr[j]   = (j == minidx) ? 0.f : wr;   // column min_idx of mk is zeroed
    }
    {
        float v = warp_min(lmin);
        if (lane == 0) sredf[wid] = v;
        __syncthreads();
        if (tid < 32) {
            float t = warp_min(sredf[tid]);
            if (tid == 0) s_min = t;
        }
        __syncthreads();
    }
    const float minv = s_min;

    // ---- w_lu_new (strictly-less -> faithful zeros) ----
#pragma unroll
    for (int p = 0; p < 8; ++p) {
        int j = tid + p * 1024;
        out[OFF_WLU + j] = (wun[p] < minv) ? 1.f : 0.f;
    }
}

// ---------------- kernel 3+4 fused: streaming update of mk and mu ----------
// EXACT Round-2/6/8 configuration (best measured: 172.2us). FROZEN.
__global__ __launch_bounds__(256) void k34_stream(const float* __restrict__ mk,
                                                  const float* __restrict__ mu,
                                                  float* __restrict__ out)
{
    const int tid  = threadIdx.x;
    const int lane = tid & 31;
    const int wid  = tid >> 5;

    const int m   = g_min_idx;
    const int m4  = m >> 2;
    const int ml  = m & 3;

    if (blockIdx.x < 1024) {
        // ---------------- mk path ----------------
        const int row = blockIdx.x * 8 + wid;
        const float4* __restrict__ src = (const float4*)mk + (size_t)row * D4;
        float4* __restrict__ dst = (float4*)(out + OFF_MK) + (size_t)row * D4;
        const float4* __restrict__ wr4 = (const float4*)g_wr;
        const float4* __restrict__ ak4 = (const float4*)g_addk;

        float acc = 0.f;
#pragma unroll 8
        for (int it = 0; it < 64; ++it) {
            const int f = lane + (it << 5);
            float4 v = src[f];
            float4 w = __ldg(wr4 + f);
            float4 a = __ldg(ak4 + f);
            // g_wr is already zero at min_idx -> no mask needed for the dot
            acc += w.x * v.x + w.y * v.y + w.z * v.z + w.w * v.w;
            float4 o = make_float4(v.x + a.x, v.y + a.y, v.z + a.z, v.w + a.w);
            if (f == m4) {   // zeroed column: output is just the added vector
                if      (ml == 0) o.x = a.x;
                else if (ml == 1) o.y = a.y;
                else if (ml == 2) o.z = a.z;
                else              o.w = a.w;
            }
            dst[f] = o;
        }
        acc = warp_sum(acc);
        if (lane == 0) out[OFF_UF + row] = acc;
    } else {
        // ---------------- mu path ----------------
        const int row = (blockIdx.x - 1024) * 8 + wid;
        const float4* __restrict__ src = (const float4*)mu + (size_t)row * D4;
        float4* __restrict__ dst = (float4*)(out + OFF_MU) + (size_t)row * D4;
        const float4* __restrict__ au4 = (const float4*)g_addu;

#pragma unroll 8
        for (int it = 0; it < 64; ++it) {
            const int f = lane + (it << 5);
            float4 v = src[f];
            float4 a = __ldg(au4 + f);
            float4 o = make_float4(v.x + a.x, v.y + a.y, v.z + a.z, v.w + a.w);
            if (f == m4) {
                if      (ml == 0) o.x = a.x;
                else if (ml == 1) o.y = a.y;
                else if (ml == 2) o.z = a.z;
                else              o.w = a.w;
            }
            dst[f] = o;
        }
    }
}

// ---------------- launch ----------------
extern "C" void kernel_launch(void* const* d_in, const int* in_sizes, int n_in,
                              void* d_out, int out_size)
{
    const float* k_in   = (const float*)d_in[0];
    const float* u_in   = (const float*)d_in[1];
    const float* mk_in  = (const float*)d_in[2];
    const float* mu_in  = (const float*)d_in[3];
    const float* ww_in  = (const float*)d_in[4];
    const float* wu_in  = (const float*)d_in[5];
    const float* wlu_in = (const float*)d_in[6];
    const float* beta_in= (const float*)d_in[7];
    float* out = (float*)d_out;

    k0_prep<<<1, 1024>>>(k_in, wu_in);
    k1_colred<<<dim3(CTILE, NSLAB), 256>>>(mk_in, k_in);
    k1b_simexp<<<64, 128>>>();
    k2_vec<<<1, 1024>>>(k_in, u_in, ww_in, wu_in, wlu_in, beta_in, out);
    k34_stream<<<2048, 256>>>(mk_in, mu_in, out);
}

// round 10
// speedup vs baseline: 1.0020x; 1.0020x over previous
#include <cuda_runtime.h>
#include <float.h>

#define D      8192
#define D4     2048          // D / 4 (float4 per row)
#define GAMMA  0.95f
#define NSLAB  64            // row slabs in kernel 1
#define RSLAB  128           // rows per slab (NSLAB * RSLAB = D)

// ---------------- device scratch (no allocations allowed) ----------------
__device__ float g_part_dot[NSLAB][D];   // fully rewritten every call
__device__ float g_part_sq [NSLAB][D];
__device__ float g_ev   [D];             // exp(sim_j), written by k1b
__device__ float g_evsum[64];            // per-block partial sums of ev
__device__ float g_minpart[64];          // per-block partial mins of w_u_new
__device__ float g_knorm;                // ||k||
__device__ float g_wr  [D];              // w_r with column min_idx zeroed
__device__ float g_addk[D];              // w_u_new * k (per column add for mk)
__device__ float g_addu[D];              // w_w_new * u (per column add for mu)
__device__ int   g_min_idx;

// output layout (element offsets into d_out, float32)
#define OFF_UF  ((size_t)0)
#define OFF_MK  ((size_t)D)
#define OFF_MU  ((size_t)D + (size_t)D * D)
#define OFF_WW  ((size_t)D + 2ull * (size_t)D * D)
#define OFF_WU  (OFF_WW + (size_t)D)
#define OFF_WLU (OFF_WU + (size_t)D)

// ---------------- warp helpers ----------------
__device__ __forceinline__ float warp_sum(float v) {
#pragma unroll
    for (int o = 16; o > 0; o >>= 1) v += __shfl_xor_sync(0xffffffffu, v, o);
    return v;
}
__device__ __forceinline__ float warp_min(float v) {
#pragma unroll
    for (int o = 16; o > 0; o >>= 1) v = fminf(v, __shfl_xor_sync(0xffffffffu, v, o));
    return v;
}

// ---------------- kernel 1: column reductions over mk + folded k0 ----------
// grid 513, block 256. Bids 0..511: EXACT Round-3 colred body (ct=bid&7,
// rs=bid>>3, 8-deep batch, __ldcs). Bid 512: computes ||k|| and
// first-index argmin(w_u) (independent of the other blocks; first consumer
// of these values is the NEXT kernel).
__global__ __launch_bounds__(256) void k1_colred(const float* __restrict__ mk,
                                                 const float* __restrict__ kvec,
                                                 const float* __restrict__ w_u)
{
    const int bid = blockIdx.x;
    const int tid = threadIdx.x;

    if (bid == 512) {
        // ---- folded k0: ||k||^2 and first-index argmin(w_u), 256 threads ----
        const int lane = tid & 31;
        const int wid  = tid >> 5;
        __shared__ float sredf[8];
        __shared__ int   sredi[8];

        float ks = 0.f;
        float bestv = FLT_MAX;
        int   besti = 0x7fffffff;
#pragma unroll 8
        for (int p = 0; p < 32; ++p) {
            int j = tid + p * 256;
            float kj = kvec[j];
            ks += kj * kj;
            float wuj = w_u[j];
            if (wuj < bestv || (wuj == bestv && j < besti)) { bestv = wuj; besti = j; }
        }
        // ||k||^2
        {
            float v = warp_sum(ks);
            if (lane == 0) sredf[wid] = v;
            __syncthreads();
            if (tid == 0) {
                float t = 0.f;
#pragma unroll
                for (int w = 0; w < 8; ++w) t += sredf[w];
                g_knorm = sqrtf(t);
            }
            __syncthreads();
        }
        // argmin (first index on ties)
        {
#pragma unroll
            for (int o = 16; o > 0; o >>= 1) {
                float ov = __shfl_xor_sync(0xffffffffu, bestv, o);
                int   oi = __shfl_xor_sync(0xffffffffu, besti, o);
                if (ov < bestv || (ov == bestv && oi < besti)) { bestv = ov; besti = oi; }
            }
            if (lane == 0) { sredf[wid] = bestv; sredi[wid] = besti; }
            __syncthreads();
            if (tid == 0) {
                float bv = sredf[0]; int bi = sredi[0];
#pragma unroll
                for (int w = 1; w < 8; ++w) {
                    if (sredf[w] < bv || (sredf[w] == bv && sredi[w] < bi)) {
                        bv = sredf[w]; bi = sredi[w];
                    }
                }
                g_min_idx = bi;
            }
        }
        return;
    }

    // ---- Round-3 colred body (FROZEN) ----
    __shared__ float sk[RSLAB];
    const int ct  = bid & 7;
    const int rs  = bid >> 3;
    const int row0 = rs * RSLAB;

    if (tid < RSLAB) sk[tid] = kvec[row0 + tid];
    __syncthreads();

    const int col4 = ct * 256 + tid;   // float4 column index within row
    const float4* __restrict__ mk4 = (const float4*)mk + (size_t)row0 * D4 + col4;

    float4 ad = make_float4(0.f, 0.f, 0.f, 0.f);
    float4 as = make_float4(0.f, 0.f, 0.f, 0.f);

    for (int r = 0; r < RSLAB; r += 8) {
        float4 v[8];
#pragma unroll
        for (int i = 0; i < 8; ++i)
            v[i] = __ldcs(mk4 + (size_t)(r + i) * D4);
#pragma unroll
        for (int i = 0; i < 8; ++i) {
            float kr = sk[r + i];
            ad.x += kr * v[i].x; ad.y += kr * v[i].y;
            ad.z += kr * v[i].z; ad.w += kr * v[i].w;
            as.x += v[i].x * v[i].x; as.y += v[i].y * v[i].y;
            as.z += v[i].z * v[i].z; as.w += v[i].w * v[i].w;
        }
    }

    ((float4*)g_part_dot[rs])[col4] = ad;
    ((float4*)g_part_sq [rs])[col4] = as;
}

// ---------------- kernel 1b: slab reduction + cosine + exp (64 x 128) -------
// sim is a cosine in [-1,1] so exp(sim) cannot overflow: the softmax
// max-subtraction is mathematically redundant (shift-invariant) and dropped.
__global__ __launch_bounds__(128) void k1b_simexp()
{
    __shared__ float sred[4];
    const int tid = threadIdx.x;
    const int j   = blockIdx.x * 128 + tid;

    float sd = 0.f, ss = 0.f;
#pragma unroll
    for (int s = 0; s < NSLAB; ++s) {
        sd += g_part_dot[s][j];
        ss += g_part_sq [s][j];
    }
    const float ev = __expf(sd / (g_knorm * sqrtf(ss)));
    g_ev[j] = ev;

    // deterministic block-level sum of ev (4 warps)
    float v = warp_sum(ev);
    if ((tid & 31) == 0) sred[tid >> 5] = v;
    __syncthreads();
    if (tid == 0)
        g_evsum[blockIdx.x] = (sred[0] + sred[1]) + (sred[2] + sred[3]);
}

// ---------------- kernel 2p: parallel vector epilogue (64 x 128) ------------
// Every block independently forms the softmax denominator from the 64
// per-block partials in the SAME deterministic order (identical result),
// then does the per-element math for its 128 j's, and writes a per-block
// min(w_u_new) partial. w_lu_new is finished inside k34's extra block.
__global__ __launch_bounds__(128) void k2p_vec(const float* __restrict__ kvec,
                                               const float* __restrict__ uvec,
                                               const float* __restrict__ w_w,
                                               const float* __restrict__ w_u,
                                               const float* __restrict__ w_lu,
                                               const float* __restrict__ beta_p,
                                               float* __restrict__ out)
{
    const int tid = threadIdx.x;
    __shared__ float s_sum;
    __shared__ float sred[4];

    if (tid < 32) {
        float t = g_evsum[tid] + g_evsum[tid + 32];
        t = warp_sum(t);
        if (tid == 0) s_sum = t;
    }
    __syncthreads();

    const float inv_sum = 1.f / s_sum;
    const float beta    = 1.f / (1.f + __expf(-beta_p[0]));
    const int   minidx  = g_min_idx;

    const int j = blockIdx.x * 128 + tid;
    const float wr     = g_ev[j] * inv_sum;
    const float wu_new = GAMMA * w_u[j] + wr + w_w[j];
    const float ww_new = beta * wr + (1.f - beta) * w_lu[j];

    out[OFF_WU + j] = wu_new;
    out[OFF_WW + j] = ww_new;
    g_addk[j] = wu_new * kvec[j];
    g_addu[j] = ww_new * uvec[j];
    g_wr[j]   = (j == minidx) ? 0.f : wr;   // column min_idx of mk is zeroed

    // per-block min(w_u_new) partial (min is exactly associative)
    float v = warp_min(wu_new);
    if ((tid & 31) == 0) sred[tid >> 5] = v;
    __syncthreads();
    if (tid == 0)
        g_minpart[blockIdx.x] = fminf(fminf(sred[0], sred[1]),
                                      fminf(sred[2], sred[3]));
}

// ---------------- kernel 3+4 fused + w_lu finisher --------------------------
// Bids 0..1023: mk path; 1024..2047: mu path (EXACT Round-2/6/8 bodies,
// FROZEN, best measured 172.2us). Bid 2048: reduce the 64 min partials and
// write w_lu_new from the wu_new values k2p stored in out.
__global__ __launch_bounds__(256) void k34_stream(const float* __restrict__ mk,
                                                  const float* __restrict__ mu,
                                                  float* __restrict__ out)
{
    const int tid  = threadIdx.x;
    const int lane = tid & 31;
    const int wid  = tid >> 5;

    if (blockIdx.x == 2048) {
        // ---- w_lu_new finisher ----
        __shared__ float s_min;
        if (tid < 32) {
            float t = fminf(g_minpart[tid], g_minpart[tid + 32]);
            t = warp_min(t);
            if (tid == 0) s_min = t;
        }
        __syncthreads();
        const float minv = s_min;
#pragma unroll 8
        for (int p = 0; p < 32; ++p) {
            int j = tid + p * 256;
            out[OFF_WLU + j] = (out[OFF_WU + j] < minv) ? 1.f : 0.f;
        }
        return;
    }

    const int m   = g_min_idx;
    const int m4  = m >> 2;
    const int ml  = m & 3;

    if (blockIdx.x < 1024) {
        // ---------------- mk path ----------------
        const int row = blockIdx.x * 8 + wid;
        const float4* __restrict__ src = (const float4*)mk + (size_t)row * D4;
        float4* __restrict__ dst = (float4*)(out + OFF_MK) + (size_t)row * D4;
        const float4* __restrict__ wr4 = (const float4*)g_wr;
        const float4* __restrict__ ak4 = (const float4*)g_addk;

        float acc = 0.f;
#pragma unroll 8
        for (int it = 0; it < 64; ++it) {
            const int f = lane + (it << 5);
            float4 v = src[f];
            float4 w = __ldg(wr4 + f);
            float4 a = __ldg(ak4 + f);
            // g_wr is already zero at min_idx -> no mask needed for the dot
            acc += w.x * v.x + w.y * v.y + w.z * v.z + w.w * v.w;
            float4 o = make_float4(v.x + a.x, v.y + a.y, v.z + a.z, v.w + a.w);
            if (f == m4) {   // zeroed column: output is just the added vector
                if      (ml == 0) o.x = a.x;
                else if (ml == 1) o.y = a.y;
                else if (ml == 2) o.z = a.z;
                else              o.w = a.w;
            }
            dst[f] = o;
        }
        acc = warp_sum(acc);
        if (lane == 0) out[OFF_UF + row] = acc;
    } else {
        // ---------------- mu path ----------------
        const int row = (blockIdx.x - 1024) * 8 + wid;
        const float4* __restrict__ src = (const float4*)mu + (size_t)row * D4;
        float4* __restrict__ dst = (float4*)(out + OFF_MU) + (size_t)row * D4;
        const float4* __restrict__ au4 = (const float4*)g_addu;

#pragma unroll 8
        for (int it = 0; it < 64; ++it) {
            const int f = lane + (it << 5);
            float4 v = src[f];
            float4 a = __ldg(au4 + f);
            float4 o = make_float4(v.x + a.x, v.y + a.y, v.z + a.z, v.w + a.w);
            if (f == m4) {
                if      (ml == 0) o.x = a.x;
                else if (ml == 1) o.y = a.y;
                else if (ml == 2) o.z = a.z;
                else              o.w = a.w;
            }
            dst[f] = o;
        }
    }
}

// ---------------- launch ----------------
extern "C" void kernel_launch(void* const* d_in, const int* in_sizes, int n_in,
                              void* d_out, int out_size)
{
    const float* k_in   = (const float*)d_in[0];
    const float* u_in   = (const float*)d_in[1];
    const float* mk_in  = (const float*)d_in[2];
    const float* mu_in  = (const float*)d_in[3];
    const float* ww_in  = (const float*)d_in[4];
    const float* wu_in  = (const float*)d_in[5];
    const float* wlu_in = (const float*)d_in[6];
    const float* beta_in= (const float*)d_in[7];
    float* out = (float*)d_out;

    k1_colred<<<513, 256>>>(mk_in, k_in, wu_in);
    k1b_simexp<<<64, 128>>>();
    k2p_vec<<<64, 128>>>(k_in, u_in, ww_in, wu_in, wlu_in, beta_in, out);
    k34_stream<<<2049, 256>>>(mk_in, mu_in, out);
}

// round 11
// speedup vs baseline: 1.0570x; 1.0548x over previous
#include <cuda_runtime.h>
#include <float.h>

#define D      8192
#define D4     2048          // D / 4 (float4 per row)
#define GAMMA  0.95f
#define NSLAB  64            // row slabs in kernel 1
#define RSLAB  128           // rows per slab (NSLAB * RSLAB = D)
#define NBLK1  513           // 512 colred blocks + 1 scalar block

// ---------------- device scratch (no allocations allowed) ----------------
__device__ float g_part_dot[NSLAB][D];   // fully rewritten every call
__device__ float g_part_sq [NSLAB][D];
__device__ float g_evsum[64];            // per-block partial sums of ev
__device__ float g_minpart[64];          // per-block partial mins of w_u_new
__device__ float g_knorm;                // ||k||
__device__ float g_wr  [D];              // w_r with column min_idx zeroed
__device__ float g_addk[D];              // w_u_new * k (per column add for mk)
__device__ float g_addu[D];              // w_w_new * u (per column add for mu)
__device__ int   g_min_idx;
// device-side barrier state (self-resetting -> graph-replay safe)
__device__ unsigned g_arr1;              // arrivals of all 513 blocks
__device__ unsigned g_arr2;              // arrivals of the 64 epilogue blocks
__device__ unsigned g_dep;               // departures of the 64 epilogue blocks

// output layout (element offsets into d_out, float32)
#define OFF_UF  ((size_t)0)
#define OFF_MK  ((size_t)D)
#define OFF_MU  ((size_t)D + (size_t)D * D)
#define OFF_WW  ((size_t)D + 2ull * (size_t)D * D)
#define OFF_WU  (OFF_WW + (size_t)D)
#define OFF_WLU (OFF_WU + (size_t)D)

// ---------------- warp helpers ----------------
__device__ __forceinline__ float warp_sum(float v) {
#pragma unroll
    for (int o = 16; o > 0; o >>= 1) v += __shfl_xor_sync(0xffffffffu, v, o);
    return v;
}
__device__ __forceinline__ float warp_min(float v) {
#pragma unroll
    for (int o = 16; o > 0; o >>= 1) v = fminf(v, __shfl_xor_sync(0xffffffffu, v, o));
    return v;
}

// ---------------- kernel 1 FUSED: colred + k0 + simexp + vector epilogue ----
// grid 513 x 256. __launch_bounds__(256,4) caps regs at 64 -> >=4 blocks/SM
// -> capacity 592 >= 513, so ALL blocks are co-resident in one wave and the
// device-side counter barrier cannot deadlock.
//   bids 0..511 : EXACT Round-3 colred body (FROZEN), then arrive.
//   bid 512     : ||k|| + first-index argmin(w_u), then arrive.
//   bids 0..63  : after barrier1, slab-reduce+cosine+exp for 128 j's each,
//                 barrier2 among the 64, then softmax denom + vector math
//                 (identical op order to R9/R10 -> identical rounding).
// Counters self-reset via the departure counter.
__global__ void __launch_bounds__(256, 4)
k1_fused(const float* __restrict__ mk,
         const float* __restrict__ kvec,
         const float* __restrict__ w_u,
         const float* __restrict__ uvec,
         const float* __restrict__ w_w,
         const float* __restrict__ w_lu,
         const float* __restrict__ beta_p,
         float* __restrict__ out)
{
    const int bid  = blockIdx.x;
    const int tid  = threadIdx.x;
    const int lane = tid & 31;
    const int wid  = tid >> 5;

    if (bid == 512) {
        // ---- scalar block: ||k||^2 and first-index argmin(w_u) ----
        __shared__ float sredf[8];
        __shared__ int   sredi[8];

        float ks = 0.f;
        float bestv = FLT_MAX;
        int   besti = 0x7fffffff;
#pragma unroll 8
        for (int p = 0; p < 32; ++p) {
            int j = tid + p * 256;
            float kj = kvec[j];
            ks += kj * kj;
            float wuj = w_u[j];
            if (wuj < bestv || (wuj == bestv && j < besti)) { bestv = wuj; besti = j; }
        }
        {
            float v = warp_sum(ks);
            if (lane == 0) sredf[wid] = v;
            __syncthreads();
            if (tid == 0) {
                float t = 0.f;
#pragma unroll
                for (int w = 0; w < 8; ++w) t += sredf[w];
                g_knorm = sqrtf(t);
            }
            __syncthreads();
        }
        {
#pragma unroll
            for (int o = 16; o > 0; o >>= 1) {
                float ov = __shfl_xor_sync(0xffffffffu, bestv, o);
                int   oi = __shfl_xor_sync(0xffffffffu, besti, o);
                if (ov < bestv || (ov == bestv && oi < besti)) { bestv = ov; besti = oi; }
            }
            if (lane == 0) { sredf[wid] = bestv; sredi[wid] = besti; }
            __syncthreads();
            if (tid == 0) {
                float bv = sredf[0]; int bi = sredi[0];
#pragma unroll
                for (int w = 1; w < 8; ++w) {
                    if (sredf[w] < bv || (sredf[w] == bv && sredi[w] < bi)) {
                        bv = sredf[w]; bi = sredi[w];
                    }
                }
                g_min_idx = bi;
            }
        }
        __syncthreads();
        __threadfence();
        if (tid == 0) atomicAdd(&g_arr1, 1u);
        return;
    }

    // ---- Round-3 colred body (FROZEN) ----
    {
        __shared__ float sk[RSLAB];
        const int ct  = bid & 7;
        const int rs  = bid >> 3;
        const int row0 = rs * RSLAB;

        if (tid < RSLAB) sk[tid] = kvec[row0 + tid];
        __syncthreads();

        const int col4 = ct * 256 + tid;
        const float4* __restrict__ mk4 = (const float4*)mk + (size_t)row0 * D4 + col4;

        float4 ad = make_float4(0.f, 0.f, 0.f, 0.f);
        float4 as = make_float4(0.f, 0.f, 0.f, 0.f);

        for (int r = 0; r < RSLAB; r += 8) {
            float4 v[8];
#pragma unroll
            for (int i = 0; i < 8; ++i)
                v[i] = __ldcs(mk4 + (size_t)(r + i) * D4);
#pragma unroll
            for (int i = 0; i < 8; ++i) {
                float kr = sk[r + i];
                ad.x += kr * v[i].x; ad.y += kr * v[i].y;
                ad.z += kr * v[i].z; ad.w += kr * v[i].w;
                as.x += v[i].x * v[i].x; as.y += v[i].y * v[i].y;
                as.z += v[i].z * v[i].z; as.w += v[i].w * v[i].w;
            }
        }

        ((float4*)g_part_dot[rs])[col4] = ad;
        ((float4*)g_part_sq [rs])[col4] = as;
    }

    __syncthreads();
    __threadfence();
    if (tid == 0) atomicAdd(&g_arr1, 1u);

    if (bid >= 64) return;   // colred-only blocks are done

    // ================= epilogue blocks 0..63 =================
    // barrier 1: wait for all 513 blocks
    if (tid == 0) {
        while (atomicAdd(&g_arr1, 0u) < (unsigned)NBLK1) __nanosleep(64);
    }
    __syncthreads();
    __threadfence();

    __shared__ float sred[4];
    __shared__ float s_sum;

    // ---- slab reduction + cosine + exp for this block's 128 j's ----
    float ev = 0.f;
    const int j = bid * 128 + tid;   // tid < 128 active
    if (tid < 128) {
        float sd = 0.f, ss = 0.f;
#pragma unroll
        for (int s = 0; s < NSLAB; ++s) {
            sd += g_part_dot[s][j];
            ss += g_part_sq [s][j];
        }
        ev = __expf(sd / (g_knorm * sqrtf(ss)));
    }
    // deterministic block sum of ev over the 4 active warps
    if (tid < 128) {
        float v = warp_sum(ev);
        if (lane == 0) sred[wid] = v;
    }
    __syncthreads();
    if (tid == 0) {
        g_evsum[bid] = (sred[0] + sred[1]) + (sred[2] + sred[3]);
        __threadfence();
        atomicAdd(&g_arr2, 1u);
    }

    // barrier 2: wait for all 64 epilogue blocks' evsum
    if (tid == 0) {
        while (atomicAdd(&g_arr2, 0u) < 64u) __nanosleep(64);
    }
    __syncthreads();
    __threadfence();

    // ---- softmax denominator (same deterministic order as R9/R10) ----
    if (tid < 32) {
        float t = g_evsum[tid] + g_evsum[tid + 32];
        t = warp_sum(t);
        if (tid == 0) s_sum = t;
    }
    __syncthreads();

    const float inv_sum = 1.f / s_sum;
    const float beta    = 1.f / (1.f + __expf(-beta_p[0]));
    const int   minidx  = g_min_idx;

    if (tid < 128) {
        const float wr     = ev * inv_sum;
        const float wu_new = GAMMA * w_u[j] + wr + w_w[j];
        const float ww_new = beta * wr + (1.f - beta) * w_lu[j];

        out[OFF_WU + j] = wu_new;
        out[OFF_WW + j] = ww_new;
        g_addk[j] = wu_new * kvec[j];
        g_addu[j] = ww_new * uvec[j];
        g_wr[j]   = (j == minidx) ? 0.f : wr;   // column min_idx of mk is zeroed

        // per-block min(w_u_new) partial (min is exactly associative)
        float v = warp_min(wu_new);
        if (lane == 0) sred[wid] = v;
    }
    __syncthreads();
    if (tid == 0) {
        g_minpart[bid] = fminf(fminf(sred[0], sred[1]), fminf(sred[2], sred[3]));
        __threadfence();
        // departure: last epilogue block resets all barrier state for the
        // next graph replay (nothing reads these counters after this point)
        unsigned d = atomicAdd(&g_dep, 1u);
        if (d == 63u) {
            atomicExch(&g_arr1, 0u);
            atomicExch(&g_arr2, 0u);
            atomicExch(&g_dep,  0u);
        }
    }
}

// ---------------- kernel 3+4 fused + w_lu finisher --------------------------
// Bids 0..1023: mk path; 1024..2047: mu path (EXACT Round-2/6/8 bodies,
// FROZEN). Bid 2048: reduce the 64 min partials and write w_lu_new.
__global__ __launch_bounds__(256) void k34_stream(const float* __restrict__ mk,
                                                  const float* __restrict__ mu,
                                                  float* __restrict__ out)
{
    const int tid  = threadIdx.x;
    const int lane = tid & 31;
    const int wid  = tid >> 5;

    if (blockIdx.x == 2048) {
        // ---- w_lu_new finisher ----
        __shared__ float s_min;
        if (tid < 32) {
            float t = fminf(g_minpart[tid], g_minpart[tid + 32]);
            t = warp_min(t);
            if (tid == 0) s_min = t;
        }
        __syncthreads();
        const float minv = s_min;
#pragma unroll 8
        for (int p = 0; p < 32; ++p) {
            int j = tid + p * 256;
            out[OFF_WLU + j] = (out[OFF_WU + j] < minv) ? 1.f : 0.f;
        }
        return;
    }

    const int m   = g_min_idx;
    const int m4  = m >> 2;
    const int ml  = m & 3;

    if (blockIdx.x < 1024) {
        // ---------------- mk path ----------------
        const int row = blockIdx.x * 8 + wid;
        const float4* __restrict__ src = (const float4*)mk + (size_t)row * D4;
        float4* __restrict__ dst = (float4*)(out + OFF_MK) + (size_t)row * D4;
        const float4* __restrict__ wr4 = (const float4*)g_wr;
        const float4* __restrict__ ak4 = (const float4*)g_addk;

        float acc = 0.f;
#pragma unroll 8
        for (int it = 0; it < 64; ++it) {
            const int f = lane + (it << 5);
            float4 v = src[f];
            float4 w = __ldg(wr4 + f);
            float4 a = __ldg(ak4 + f);
            // g_wr is already zero at min_idx -> no mask needed for the dot
            acc += w.x * v.x + w.y * v.y + w.z * v.z + w.w * v.w;
            float4 o = make_float4(v.x + a.x, v.y + a.y, v.z + a.z, v.w + a.w);
            if (f == m4) {   // zeroed column: output is just the added vector
                if      (ml == 0) o.x = a.x;
                else if (ml == 1) o.y = a.y;
                else if (ml == 2) o.z = a.z;
                else              o.w = a.w;
            }
            dst[f] = o;
        }
        acc = warp_sum(acc);
        if (lane == 0) out[OFF_UF + row] = acc;
    } else {
        // ---------------- mu path ----------------
        const int row = (blockIdx.x - 1024) * 8 + wid;
        const float4* __restrict__ src = (const float4*)mu + (size_t)row * D4;
        float4* __restrict__ dst = (float4*)(out + OFF_MU) + (size_t)row * D4;
        const float4* __restrict__ au4 = (const float4*)g_addu;

#pragma unroll 8
        for (int it = 0; it < 64; ++it) {
            const int f = lane + (it << 5);
            float4 v = src[f];
            float4 a = __ldg(au4 + f);
            float4 o = make_float4(v.x + a.x, v.y + a.y, v.z + a.z, v.w + a.w);
            if (f == m4) {
                if      (ml == 0) o.x = a.x;
                else if (ml == 1) o.y = a.y;
                else if (ml == 2) o.z = a.z;
                else              o.w = a.w;
            }
            dst[f] = o;
        }
    }
}

// ---------------- launch ----------------
extern "C" void kernel_launch(void* const* d_in, const int* in_sizes, int n_in,
                              void* d_out, int out_size)
{
    const float* k_in   = (const float*)d_in[0];
    const float* u_in   = (const float*)d_in[1];
    const float* mk_in  = (const float*)d_in[2];
    const float* mu_in  = (const float*)d_in[3];
    const float* ww_in  = (const float*)d_in[4];
    const float* wu_in  = (const float*)d_in[5];
    const float* wlu_in = (const float*)d_in[6];
    const float* beta_in= (const float*)d_in[7];
    float* out = (float*)d_out;

    k1_fused<<<NBLK1, 256>>>(mk_in, k_in, wu_in, u_in, ww_in, wlu_in, beta_in, out);
    k34_stream<<<2049, 256>>>(mk_in, mu_in, out);
}

// round 12
// speedup vs baseline: 1.0620x; 1.0048x over previous
#include <cuda_runtime.h>
#include <float.h>

#define D      8192
#define D4     2048          // D / 4 (float4 per row)
#define GAMMA  0.95f
#define NSLAB  64            // row slabs in kernel 1
#define RSLAB  128           // rows per slab (NSLAB * RSLAB = D)
#define NBLK1  513           // 512 colred blocks + 1 scalar block

// ---------------- device scratch (no allocations allowed) ----------------
__device__ float g_part_dot[NSLAB][D];   // fully rewritten every call
__device__ float g_part_sq [NSLAB][D];
__device__ float g_evsum[64];            // per-block partial sums of ev
__device__ float g_minpart[64];          // per-block partial mins of w_u_new
__device__ float g_knorm;                // ||k||
__device__ float g_wr  [D];              // w_r with column min_idx zeroed
__device__ float g_addk[D];              // w_u_new * k (per column add for mk)
__device__ float g_addu[D];              // w_w_new * u (per column add for mu)
__device__ int   g_min_idx;
// device-side barrier state (self-resetting -> graph-replay safe)
__device__ unsigned g_arr1;              // arrivals of all 513 blocks
__device__ unsigned g_arr2;              // arrivals of the 64 epilogue blocks
__device__ unsigned g_dep;               // departures of the 64 epilogue blocks

// output layout (element offsets into d_out, float32)
#define OFF_UF  ((size_t)0)
#define OFF_MK  ((size_t)D)
#define OFF_MU  ((size_t)D + (size_t)D * D)
#define OFF_WW  ((size_t)D + 2ull * (size_t)D * D)
#define OFF_WU  (OFF_WW + (size_t)D)
#define OFF_WLU (OFF_WU + (size_t)D)

// ---------------- warp helpers ----------------
__device__ __forceinline__ float warp_sum(float v) {
#pragma unroll
    for (int o = 16; o > 0; o >>= 1) v += __shfl_xor_sync(0xffffffffu, v, o);
    return v;
}
__device__ __forceinline__ float warp_min(float v) {
#pragma unroll
    for (int o = 16; o > 0; o >>= 1) v = fminf(v, __shfl_xor_sync(0xffffffffu, v, o));
    return v;
}

// ---------------- kernel 1 FUSED: colred + k0 + simexp + vector epilogue ----
// grid 513 x 256. __launch_bounds__(256,4) -> >=4 blocks/SM -> capacity 592
// >= 513: all blocks co-resident, counter barrier deadlock-free.
//   bids 0..511 : EXACT Round-3 colred body (FROZEN), then arrive.
//   bid 512     : ||k|| + first-index argmin(w_u), then arrive.
//   bids 0..63  : after barrier1, slab-reduce (256 threads, 2 half-slab
//                 partials per j pair-combined in smem) + cosine + exp,
//                 barrier2 among the 64, then softmax denom + vector math.
__global__ void __launch_bounds__(256, 4)
k1_fused(const float* __restrict__ mk,
         const float* __restrict__ kvec,
         const float* __restrict__ w_u,
         const float* __restrict__ uvec,
         const float* __restrict__ w_w,
         const float* __restrict__ w_lu,
         const float* __restrict__ beta_p,
         float* __restrict__ out)
{
    const int bid  = blockIdx.x;
    const int tid  = threadIdx.x;
    const int lane = tid & 31;
    const int wid  = tid >> 5;

    if (bid == 512) {
        // ---- scalar block: ||k||^2 and first-index argmin(w_u) ----
        __shared__ float sredf[8];
        __shared__ int   sredi[8];

        float ks = 0.f;
        float bestv = FLT_MAX;
        int   besti = 0x7fffffff;
#pragma unroll 8
        for (int p = 0; p < 32; ++p) {
            int j = tid + p * 256;
            float kj = kvec[j];
            ks += kj * kj;
            float wuj = w_u[j];
            if (wuj < bestv || (wuj == bestv && j < besti)) { bestv = wuj; besti = j; }
        }
        {
            float v = warp_sum(ks);
            if (lane == 0) sredf[wid] = v;
            __syncthreads();
            if (tid == 0) {
                float t = 0.f;
#pragma unroll
                for (int w = 0; w < 8; ++w) t += sredf[w];
                g_knorm = sqrtf(t);
            }
            __syncthreads();
        }
        {
#pragma unroll
            for (int o = 16; o > 0; o >>= 1) {
                float ov = __shfl_xor_sync(0xffffffffu, bestv, o);
                int   oi = __shfl_xor_sync(0xffffffffu, besti, o);
                if (ov < bestv || (ov == bestv && oi < besti)) { bestv = ov; besti = oi; }
            }
            if (lane == 0) { sredf[wid] = bestv; sredi[wid] = besti; }
            __syncthreads();
            if (tid == 0) {
                float bv = sredf[0]; int bi = sredi[0];
#pragma unroll
                for (int w = 1; w < 8; ++w) {
                    if (sredf[w] < bv || (sredf[w] == bv && sredi[w] < bi)) {
                        bv = sredf[w]; bi = sredi[w];
                    }
                }
                g_min_idx = bi;
            }
        }
        __syncthreads();
        __threadfence();
        if (tid == 0) atomicAdd(&g_arr1, 1u);
        return;
    }

    // ---- Round-3 colred body (FROZEN) ----
    {
        __shared__ float sk[RSLAB];
        const int ct  = bid & 7;
        const int rs  = bid >> 3;
        const int row0 = rs * RSLAB;

        if (tid < RSLAB) sk[tid] = kvec[row0 + tid];
        __syncthreads();

        const int col4 = ct * 256 + tid;
        const float4* __restrict__ mk4 = (const float4*)mk + (size_t)row0 * D4 + col4;

        float4 ad = make_float4(0.f, 0.f, 0.f, 0.f);
        float4 as = make_float4(0.f, 0.f, 0.f, 0.f);

        for (int r = 0; r < RSLAB; r += 8) {
            float4 v[8];
#pragma unroll
            for (int i = 0; i < 8; ++i)
                v[i] = __ldcs(mk4 + (size_t)(r + i) * D4);
#pragma unroll
            for (int i = 0; i < 8; ++i) {
                float kr = sk[r + i];
                ad.x += kr * v[i].x; ad.y += kr * v[i].y;
                ad.z += kr * v[i].z; ad.w += kr * v[i].w;
                as.x += v[i].x * v[i].x; as.y += v[i].y * v[i].y;
                as.z += v[i].z * v[i].z; as.w += v[i].w * v[i].w;
            }
        }

        ((float4*)g_part_dot[rs])[col4] = ad;
        ((float4*)g_part_sq [rs])[col4] = as;
    }

    __syncthreads();
    __threadfence();
    if (tid == 0) atomicAdd(&g_arr1, 1u);

    if (bid >= 64) return;   // colred-only blocks are done

    // ================= epilogue blocks 0..63 =================
    // barrier 1: wait for all 513 blocks
    if (tid == 0) {
        while (atomicAdd(&g_arr1, 0u) < (unsigned)NBLK1) __nanosleep(64);
    }
    __syncthreads();
    __threadfence();

    __shared__ float sred[4];
    __shared__ float s_sum;
    __shared__ float shalf_d[128];
    __shared__ float shalf_s[128];

    // ---- slab reduction with 256 threads: tid<128 sums slabs 0..31 for
    //      j = bid*128+tid; tid>=128 sums slabs 32..63 for the same j and
    //      deposits in smem; halves pair-combined by the low threads. ----
    const int jl   = tid & 127;          // j within this block
    const int half = tid >> 7;           // 0 or 1
    const int j    = bid * 128 + jl;
    {
        float sd = 0.f, ss = 0.f;
        const int s0 = half * 32;
#pragma unroll
        for (int s = 0; s < 32; ++s) {
            sd += g_part_dot[s0 + s][j];
            ss += g_part_sq [s0 + s][j];
        }
        if (half == 1) { shalf_d[jl] = sd; shalf_s[jl] = ss; }
        __syncthreads();
        if (half == 0) { shalf_d[jl] += sd; shalf_s[jl] += ss; } // low+high? no:
        // NOTE: order = (slabs 0..31) + (slabs 32..63): we add high-half from
        // smem to the low-half register value below.
    }
    __syncthreads();

    float ev = 0.f;
    if (tid < 128) {
        // shalf now holds hi-half added into lo-half? We wrote hi to smem,
        // then low threads added their lo value INTO smem -> smem = lo+hi.
        const float sd = shalf_d[jl];
        const float ss = shalf_s[jl];
        ev = __expf(sd / (g_knorm * sqrtf(ss)));
        // deterministic block sum of ev over the 4 active warps
        float v = warp_sum(ev);
        if (lane == 0) sred[wid] = v;
    }
    __syncthreads();
    if (tid == 0) {
        g_evsum[bid] = (sred[0] + sred[1]) + (sred[2] + sred[3]);
        __threadfence();
        atomicAdd(&g_arr2, 1u);
    }

    // barrier 2: wait for all 64 epilogue blocks' evsum
    if (tid == 0) {
        while (atomicAdd(&g_arr2, 0u) < 64u) __nanosleep(64);
    }
    __syncthreads();
    __threadfence();

    // ---- softmax denominator (same deterministic order as R9-R11) ----
    if (tid < 32) {
        float t = g_evsum[tid] + g_evsum[tid + 32];
        t = warp_sum(t);
        if (tid == 0) s_sum = t;
    }
    __syncthreads();

    const float inv_sum = 1.f / s_sum;
    const float beta    = 1.f / (1.f + __expf(-beta_p[0]));
    const int   minidx  = g_min_idx;

    if (tid < 128) {
        const float wr     = ev * inv_sum;
        const float wu_new = GAMMA * w_u[j] + wr + w_w[j];
        const float ww_new = beta * wr + (1.f - beta) * w_lu[j];

        out[OFF_WU + j] = wu_new;
        out[OFF_WW + j] = ww_new;
        g_addk[j] = wu_new * kvec[j];
        g_addu[j] = ww_new * uvec[j];
        g_wr[j]   = (j == minidx) ? 0.f : wr;   // column min_idx of mk is zeroed

        // per-block min(w_u_new) partial (min is exactly associative)
        float v = warp_min(wu_new);
        if (lane == 0) sred[wid] = v;
    }
    __syncthreads();
    if (tid == 0) {
        g_minpart[bid] = fminf(fminf(sred[0], sred[1]), fminf(sred[2], sred[3]));
        __threadfence();
        // departure: last epilogue block resets all barrier state for the
        // next graph replay
        unsigned d = atomicAdd(&g_dep, 1u);
        if (d == 63u) {
            atomicExch(&g_arr1, 0u);
            atomicExch(&g_arr2, 0u);
            atomicExch(&g_dep,  0u);
        }
    }
}

// ---------------- kernel 3+4 fused + w_lu finisher --------------------------
// Bids 0..1023: mk path; 1024..2047: mu path (EXACT Round-2/6/8 bodies,
// FROZEN). Bid 2048: reduce the 64 min partials and write w_lu_new.
__global__ __launch_bounds__(256) void k34_stream(const float* __restrict__ mk,
                                                  const float* __restrict__ mu,
                                                  float* __restrict__ out)
{
    const int tid  = threadIdx.x;
    const int lane = tid & 31;
    const int wid  = tid >> 5;

    if (blockIdx.x == 2048) {
        // ---- w_lu_new finisher ----
        __shared__ float s_min;
        if (tid < 32) {
            float t = fminf(g_minpart[tid], g_minpart[tid + 32]);
            t = warp_min(t);
            if (tid == 0) s_min = t;
        }
        __syncthreads();
        const float minv = s_min;
#pragma unroll 8
        for (int p = 0; p < 32; ++p) {
            int j = tid + p * 256;
            out[OFF_WLU + j] = (out[OFF_WU + j] < minv) ? 1.f : 0.f;
        }
        return;
    }

    const int m   = g_min_idx;
    const int m4  = m >> 2;
    const int ml  = m & 3;

    if (blockIdx.x < 1024) {
        // ---------------- mk path ----------------
        const int row = blockIdx.x * 8 + wid;
        const float4* __restrict__ src = (const float4*)mk + (size_t)row * D4;
        float4* __restrict__ dst = (float4*)(out + OFF_MK) + (size_t)row * D4;
        const float4* __restrict__ wr4 = (const float4*)g_wr;
        const float4* __restrict__ ak4 = (const float4*)g_addk;

        float acc = 0.f;
#pragma unroll 8
        for (int it = 0; it < 64; ++it) {
            const int f = lane + (it << 5);
            float4 v = src[f];
            float4 w = __ldg(wr4 + f);
            float4 a = __ldg(ak4 + f);
            // g_wr is already zero at min_idx -> no mask needed for the dot
            acc += w.x * v.x + w.y * v.y + w.z * v.z + w.w * v.w;
            float4 o = make_float4(v.x + a.x, v.y + a.y, v.z + a.z, v.w + a.w);
            if (f == m4) {   // zeroed column: output is just the added vector
                if      (ml == 0) o.x = a.x;
                else if (ml == 1) o.y = a.y;
                else if (ml == 2) o.z = a.z;
                else              o.w = a.w;
            }
            dst[f] = o;
        }
        acc = warp_sum(acc);
        if (lane == 0) out[OFF_UF + row] = acc;
    } else {
        // ---------------- mu path ----------------
        const int row = (blockIdx.x - 1024) * 8 + wid;
        const float4* __restrict__ src = (const float4*)mu + (size_t)row * D4;
        float4* __restrict__ dst = (float4*)(out + OFF_MU) + (size_t)row * D4;
        const float4* __restrict__ au4 = (const float4*)g_addu;

#pragma unroll 8
        for (int it = 0; it < 64; ++it) {
            const int f = lane + (it << 5);
            float4 v = src[f];
            float4 a = __ldg(au4 + f);
            float4 o = make_float4(v.x + a.x, v.y + a.y, v.z + a.z, v.w + a.w);
            if (f == m4) {
                if      (ml == 0) o.x = a.x;
                else if (ml == 1) o.y = a.y;
                else if (ml == 2) o.z = a.z;
                else              o.w = a.w;
            }
            dst[f] = o;
        }
    }
}

// ---------------- launch ----------------
extern "C" void kernel_launch(void* const* d_in, const int* in_sizes, int n_in,
                              void* d_out, int out_size)
{
    const float* k_in   = (const float*)d_in[0];
    const float* u_in   = (const float*)d_in[1];
    const float* mk_in  = (const float*)d_in[2];
    const float* mu_in  = (const float*)d_in[3];
    const float* ww_in  = (const float*)d_in[4];
    const float* wu_in  = (const float*)d_in[5];
    const float* wlu_in = (const float*)d_in[6];
    const float* beta_in= (const float*)d_in[7];
    float* out = (float*)d_out;

    k1_fused<<<NBLK1, 256>>>(mk_in, k_in, wu_in, u_in, ww_in, wlu_in, beta_in, out);
    k34_stream<<<2049, 256>>>(mk_in, mu_in, out);
}

// round 13
// speedup vs baseline: 1.0637x; 1.0016x over previous
#include <cuda_runtime.h>
#include <float.h>

#define D      8192
#define D4     2048          // D / 4 (float4 per row)
#define GAMMA  0.95f
#define NSLAB  64            // row slabs in kernel 1
#define RSLAB  128           // rows per slab (NSLAB * RSLAB = D)
#define NBLK1  513           // 512 colred blocks + 1 scalar block

// ---------------- device scratch (no allocations allowed) ----------------
__device__ float g_part_dot[NSLAB][D];   // fully rewritten every call
__device__ float g_part_sq [NSLAB][D];
__device__ float g_evsum[64];            // per-block partial sums of ev
__device__ float g_minpart[64];          // per-block partial mins of w_u_new
__device__ float g_knorm;                // ||k||
__device__ float g_wr  [D];              // w_r with column min_idx zeroed
__device__ float g_addk[D];              // w_u_new * k (per column add for mk)
__device__ float g_addu[D];              // w_w_new * u (per column add for mu)
__device__ int   g_min_idx;
// device-side barrier state (self-resetting -> graph-replay safe)
__device__ unsigned g_arr1;              // arrivals of all 513 blocks
__device__ unsigned g_arr2;              // arrivals of the 64 epilogue blocks
__device__ unsigned g_dep;               // departures of the 64 epilogue blocks

// output layout (element offsets into d_out, float32)
#define OFF_UF  ((size_t)0)
#define OFF_MK  ((size_t)D)
#define OFF_MU  ((size_t)D + (size_t)D * D)
#define OFF_WW  ((size_t)D + 2ull * (size_t)D * D)
#define OFF_WU  (OFF_WW + (size_t)D)
#define OFF_WLU (OFF_WU + (size_t)D)

// ---------------- warp helpers ----------------
__device__ __forceinline__ float warp_sum(float v) {
#pragma unroll
    for (int o = 16; o > 0; o >>= 1) v += __shfl_xor_sync(0xffffffffu, v, o);
    return v;
}
__device__ __forceinline__ float warp_min(float v) {
#pragma unroll
    for (int o = 16; o > 0; o >>= 1) v = fminf(v, __shfl_xor_sync(0xffffffffu, v, o));
    return v;
}

// ---------------- kernel 1 FUSED: colred + k0 + simexp + vector epilogue ----
// grid 513 x 256. __launch_bounds__(256,4) -> >=4 blocks/SM -> capacity 592
// >= 513: all blocks co-resident, counter barrier deadlock-free.
// EXACT Round-12 body (FROZEN).
__global__ void __launch_bounds__(256, 4)
k1_fused(const float* __restrict__ mk,
         const float* __restrict__ kvec,
         const float* __restrict__ w_u,
         const float* __restrict__ uvec,
         const float* __restrict__ w_w,
         const float* __restrict__ w_lu,
         const float* __restrict__ beta_p,
         float* __restrict__ out)
{
    const int bid  = blockIdx.x;
    const int tid  = threadIdx.x;
    const int lane = tid & 31;
    const int wid  = tid >> 5;

    if (bid == 512) {
        // ---- scalar block: ||k||^2 and first-index argmin(w_u) ----
        __shared__ float sredf[8];
        __shared__ int   sredi[8];

        float ks = 0.f;
        float bestv = FLT_MAX;
        int   besti = 0x7fffffff;
#pragma unroll 8
        for (int p = 0; p < 32; ++p) {
            int j = tid + p * 256;
            float kj = kvec[j];
            ks += kj * kj;
            float wuj = w_u[j];
            if (wuj < bestv || (wuj == bestv && j < besti)) { bestv = wuj; besti = j; }
        }
        {
            float v = warp_sum(ks);
            if (lane == 0) sredf[wid] = v;
            __syncthreads();
            if (tid == 0) {
                float t = 0.f;
#pragma unroll
                for (int w = 0; w < 8; ++w) t += sredf[w];
                g_knorm = sqrtf(t);
            }
            __syncthreads();
        }
        {
#pragma unroll
            for (int o = 16; o > 0; o >>= 1) {
                float ov = __shfl_xor_sync(0xffffffffu, bestv, o);
                int   oi = __shfl_xor_sync(0xffffffffu, besti, o);
                if (ov < bestv || (ov == bestv && oi < besti)) { bestv = ov; besti = oi; }
            }
            if (lane == 0) { sredf[wid] = bestv; sredi[wid] = besti; }
            __syncthreads();
            if (tid == 0) {
                float bv = sredf[0]; int bi = sredi[0];
#pragma unroll
                for (int w = 1; w < 8; ++w) {
                    if (sredf[w] < bv || (sredf[w] == bv && sredi[w] < bi)) {
                        bv = sredf[w]; bi = sredi[w];
                    }
                }
                g_min_idx = bi;
            }
        }
        __syncthreads();
        __threadfence();
        if (tid == 0) atomicAdd(&g_arr1, 1u);
        return;
    }

    // ---- Round-3 colred body (FROZEN) ----
    {
        __shared__ float sk[RSLAB];
        const int ct  = bid & 7;
        const int rs  = bid >> 3;
        const int row0 = rs * RSLAB;

        if (tid < RSLAB) sk[tid] = kvec[row0 + tid];
        __syncthreads();

        const int col4 = ct * 256 + tid;
        const float4* __restrict__ mk4 = (const float4*)mk + (size_t)row0 * D4 + col4;

        float4 ad = make_float4(0.f, 0.f, 0.f, 0.f);
        float4 as = make_float4(0.f, 0.f, 0.f, 0.f);

        for (int r = 0; r < RSLAB; r += 8) {
            float4 v[8];
#pragma unroll
            for (int i = 0; i < 8; ++i)
                v[i] = __ldcs(mk4 + (size_t)(r + i) * D4);
#pragma unroll
            for (int i = 0; i < 8; ++i) {
                float kr = sk[r + i];
                ad.x += kr * v[i].x; ad.y += kr * v[i].y;
                ad.z += kr * v[i].z; ad.w += kr * v[i].w;
                as.x += v[i].x * v[i].x; as.y += v[i].y * v[i].y;
                as.z += v[i].z * v[i].z; as.w += v[i].w * v[i].w;
            }
        }

        ((float4*)g_part_dot[rs])[col4] = ad;
        ((float4*)g_part_sq [rs])[col4] = as;
    }

    __syncthreads();
    __threadfence();
    if (tid == 0) atomicAdd(&g_arr1, 1u);

    if (bid >= 64) return;   // colred-only blocks are done

    // ================= epilogue blocks 0..63 =================
    if (tid == 0) {
        while (atomicAdd(&g_arr1, 0u) < (unsigned)NBLK1) __nanosleep(64);
    }
    __syncthreads();
    __threadfence();

    __shared__ float sred[4];
    __shared__ float s_sum;
    __shared__ float shalf_d[128];
    __shared__ float shalf_s[128];

    // ---- slab reduction with 256 threads (two half-slab partials per j) ----
    const int jl   = tid & 127;
    const int half = tid >> 7;
    const int j    = bid * 128 + jl;
    {
        float sd = 0.f, ss = 0.f;
        const int s0 = half * 32;
#pragma unroll
        for (int s = 0; s < 32; ++s) {
            sd += g_part_dot[s0 + s][j];
            ss += g_part_sq [s0 + s][j];
        }
        if (half == 1) { shalf_d[jl] = sd; shalf_s[jl] = ss; }
        __syncthreads();
        if (half == 0) { shalf_d[jl] += sd; shalf_s[jl] += ss; }
    }
    __syncthreads();

    float ev = 0.f;
    if (tid < 128) {
        const float sd = shalf_d[jl];
        const float ss = shalf_s[jl];
        ev = __expf(sd / (g_knorm * sqrtf(ss)));
        float v = warp_sum(ev);
        if (lane == 0) sred[wid] = v;
    }
    __syncthreads();
    if (tid == 0) {
        g_evsum[bid] = (sred[0] + sred[1]) + (sred[2] + sred[3]);
        __threadfence();
        atomicAdd(&g_arr2, 1u);
    }

    if (tid == 0) {
        while (atomicAdd(&g_arr2, 0u) < 64u) __nanosleep(64);
    }
    __syncthreads();
    __threadfence();

    // ---- softmax denominator (same deterministic order as R9-R12) ----
    if (tid < 32) {
        float t = g_evsum[tid] + g_evsum[tid + 32];
        t = warp_sum(t);
        if (tid == 0) s_sum = t;
    }
    __syncthreads();

    const float inv_sum = 1.f / s_sum;
    const float beta    = 1.f / (1.f + __expf(-beta_p[0]));
    const int   minidx  = g_min_idx;

    if (tid < 128) {
        const float wr     = ev * inv_sum;
        const float wu_new = GAMMA * w_u[j] + wr + w_w[j];
        const float ww_new = beta * wr + (1.f - beta) * w_lu[j];

        out[OFF_WU + j] = wu_new;
        out[OFF_WW + j] = ww_new;
        g_addk[j] = wu_new * kvec[j];
        g_addu[j] = ww_new * uvec[j];
        g_wr[j]   = (j == minidx) ? 0.f : wr;

        float v = warp_min(wu_new);
        if (lane == 0) sred[wid] = v;
    }
    __syncthreads();
    if (tid == 0) {
        g_minpart[bid] = fminf(fminf(sred[0], sred[1]), fminf(sred[2], sred[3]));
        __threadfence();
        unsigned d = atomicAdd(&g_dep, 1u);
        if (d == 63u) {
            atomicExch(&g_arr1, 0u);
            atomicExch(&g_arr2, 0u);
            atomicExch(&g_dep,  0u);
        }
    }
}

// ---------------- kernel 3+4 fused + w_lu finisher (PDL secondary) ----------
// Launched with ProgrammaticStreamSerialization: blocks may be scheduled
// while k1_fused is still running; cudaGridDependencySynchronize() blocks
// until k1_fused's writes are visible. Body after the sync is byte-identical
// to the frozen Round-12 version.
__global__ __launch_bounds__(256) void k34_stream(const float* __restrict__ mk,
                                                  const float* __restrict__ mu,
                                                  float* __restrict__ out)
{
#if __CUDA_ARCH__ >= 900
    cudaGridDependencySynchronize();
#endif

    const int tid  = threadIdx.x;
    const int lane = tid & 31;
    const int wid  = tid >> 5;

    if (blockIdx.x == 2048) {
        // ---- w_lu_new finisher ----
        __shared__ float s_min;
        if (tid < 32) {
            float t = fminf(g_minpart[tid], g_minpart[tid + 32]);
            t = warp_min(t);
            if (tid == 0) s_min = t;
        }
        __syncthreads();
        const float minv = s_min;
#pragma unroll 8
        for (int p = 0; p < 32; ++p) {
            int j = tid + p * 256;
            out[OFF_WLU + j] = (out[OFF_WU + j] < minv) ? 1.f : 0.f;
        }
        return;
    }

    const int m   = g_min_idx;
    const int m4  = m >> 2;
    const int ml  = m & 3;

    if (blockIdx.x < 1024) {
        // ---------------- mk path ----------------
        const int row = blockIdx.x * 8 + wid;
        const float4* __restrict__ src = (const float4*)mk + (size_t)row * D4;
        float4* __restrict__ dst = (float4*)(out + OFF_MK) + (size_t)row * D4;
        const float4* __restrict__ wr4 = (const float4*)g_wr;
        const float4* __restrict__ ak4 = (const float4*)g_addk;

        float acc = 0.f;
#pragma unroll 8
        for (int it = 0; it < 64; ++it) {
            const int f = lane + (it << 5);
            float4 v = src[f];
            float4 w = __ldg(wr4 + f);
            float4 a = __ldg(ak4 + f);
            acc += w.x * v.x + w.y * v.y + w.z * v.z + w.w * v.w;
            float4 o = make_float4(v.x + a.x, v.y + a.y, v.z + a.z, v.w + a.w);
            if (f == m4) {
                if      (ml == 0) o.x = a.x;
                else if (ml == 1) o.y = a.y;
                else if (ml == 2) o.z = a.z;
                else              o.w = a.w;
            }
            dst[f] = o;
        }
        acc = warp_sum(acc);
        if (lane == 0) out[OFF_UF + row] = acc;
    } else {
        // ---------------- mu path ----------------
        const int row = (blockIdx.x - 1024) * 8 + wid;
        const float4* __restrict__ src = (const float4*)mu + (size_t)row * D4;
        float4* __restrict__ dst = (float4*)(out + OFF_MU) + (size_t)row * D4;
        const float4* __restrict__ au4 = (const float4*)g_addu;

#pragma unroll 8
        for (int it = 0; it < 64; ++it) {
            const int f = lane + (it << 5);
            float4 v = src[f];
            float4 a = __ldg(au4 + f);
            float4 o = make_float4(v.x + a.x, v.y + a.y, v.z + a.z, v.w + a.w);
            if (f == m4) {
                if      (ml == 0) o.x = a.x;
                else if (ml == 1) o.y = a.y;
                else if (ml == 2) o.z = a.z;
                else              o.w = a.w;
            }
            dst[f] = o;
        }
    }
}

// ---------------- launch ----------------
extern "C" void kernel_launch(void* const* d_in, const int* in_sizes, int n_in,
                              void* d_out, int out_size)
{
    const float* k_in   = (const float*)d_in[0];
    const float* u_in   = (const float*)d_in[1];
    const float* mk_in  = (const float*)d_in[2];
    const float* mu_in  = (const float*)d_in[3];
    const float* ww_in  = (const float*)d_in[4];
    const float* wu_in  = (const float*)d_in[5];
    const float* wlu_in = (const float*)d_in[6];
    const float* beta_in= (const float*)d_in[7];
    float* out = (float*)d_out;

    k1_fused<<<NBLK1, 256>>>(mk_in, k_in, wu_in, u_in, ww_in, wlu_in, beta_in, out);

    // PDL launch of k34: scheduled early, gridsync gates data consumption.
    cudaLaunchConfig_t cfg = {};
    cfg.gridDim  = dim3(2049, 1, 1);
    cfg.blockDim = dim3(256, 1, 1);
    cfg.dynamicSmemBytes = 0;
    cfg.stream = 0;
    cudaLaunchAttribute attrs[1];
    attrs[0].id = cudaLaunchAttributeProgrammaticStreamSerialization;
    attrs[0].val.programmaticStreamSerializationAllowed = 1;
    cfg.attrs = attrs;
    cfg.numAttrs = 1;
    cudaLaunchKernelEx(&cfg, k34_stream, mk_in, mu_in, out);
}